// round 6
// baseline (speedup 1.0000x reference)
#include <cuda_runtime.h>
#include <cstdint>

// Problem constants
#define DD   256
#define NQ   4
#define KK   1024
#define NTOT 131072

// Tiling
#define BM   64               // rows per CTA (8 warps x 8 rows)
#define BNC  256              // codes per chunk (whole warp covers all of them)
#define BK   32               // d per staged chunk
#define NTHREADS 256
#define NITER 32              // 4 cc * 8 dk

// Scratch
__device__ float g_res[(size_t)NTOT * DD];      // residual, row-major [n][d]
__device__ float g_cbT[(size_t)NQ * DD * KK];   // codebooks transposed [s][d][k]
__device__ float g_c2[NQ * KK];                 // ||c||^2 per code

// ---------------- packed f32x2 helpers ----------------
__device__ __forceinline__ unsigned long long pack2(float x) {
    unsigned long long r;
    unsigned int xi = __float_as_uint(x);
    asm("mov.b64 %0, {%1, %1};" : "=l"(r) : "r"(xi));
    return r;
}
__device__ __forceinline__ void ffma2(unsigned long long &acc,
                                      unsigned long long a,
                                      unsigned long long b) {
    asm("fma.rn.f32x2 %0, %1, %2, %0;" : "+l"(acc) : "l"(a), "l"(b));
}
__device__ __forceinline__ float2 unpack2(unsigned long long v) {
    unsigned int lo, hi;
    asm("mov.b64 {%0, %1}, %2;" : "=r"(lo), "=r"(hi) : "l"(v));
    return make_float2(__uint_as_float(lo), __uint_as_float(hi));
}
__device__ __forceinline__ void cpasync16(uint32_t s, const void* g) {
    asm volatile("cp.async.cg.shared.global [%0], [%1], 16;" :: "r"(s), "l"(g));
}

// ---------------- generic 32x32 tiled transpose: src[R][C] -> dst[C][R] ----------------
__global__ void transpose_k(const float* __restrict__ src, float* __restrict__ dst,
                            int R, int C, long srcBatch, long dstBatch) {
    __shared__ float tile[32][33];
    const float* s = src + (long)blockIdx.z * srcBatch;
    float*       d = dst + (long)blockIdx.z * dstBatch;
    int c0 = blockIdx.x * 32, r0 = blockIdx.y * 32;
    int tx = threadIdx.x, ty = threadIdx.y;           // 32 x 8
    #pragma unroll
    for (int i = 0; i < 32; i += 8)
        tile[ty + i][tx] = s[(long)(r0 + ty + i) * C + c0 + tx];
    __syncthreads();
    #pragma unroll
    for (int i = 0; i < 32; i += 8)
        d[(long)(c0 + ty + i) * R + r0 + tx] = tile[tx][ty + i];
}

// ---------------- ||c||^2 per code ----------------
__global__ void c2_k(const float* __restrict__ cb) {
    int w = (blockIdx.x * blockDim.x + threadIdx.x) >> 5;
    int lane = threadIdx.x & 31;
    if (w >= NQ * KK) return;
    const float* row = cb + (long)w * DD;
    float s = 0.f;
    #pragma unroll
    for (int j = lane; j < DD; j += 32) { float v = row[j]; s = fmaf(v, v, s); }
    #pragma unroll
    for (int o = 16; o; o >>= 1) s += __shfl_xor_sync(0xffffffffu, s, o);
    if (lane == 0) g_c2[w] = s;
}

__global__ void copy_res_k(const float* __restrict__ x) {
    size_t i = (size_t)blockIdx.x * blockDim.x + threadIdx.x;
    ((float4*)g_res)[i] = ((const float4*)x)[i];
}
__global__ void finalize_k(const float* __restrict__ x, float* __restrict__ out) {
    size_t i = (size_t)blockIdx.x * blockDim.x + threadIdx.x;
    float4 xv = ((const float4*)x)[i];
    float4 rv = ((const float4*)g_res)[i];
    float4 o; o.x = xv.x - rv.x; o.y = xv.y - rv.y; o.z = xv.z - rv.z; o.w = xv.w - rv.w;
    ((float4*)out)[i] = o;
}

// ---------------- main per-stage kernel ----------------
// 8 warps. Warp w owns rows w*8..w*8+7, all 256 codes of each chunk.
// Lane l owns codes {cc*256 + l*4 + q} and {cc*256 + 128 + l*4 + q}, q=0..3.
// A is held in registers (lane l holds A[8 rows] at d = dk*32 + l), broadcast via shfl.
__global__ void __launch_bounds__(NTHREADS, 2)
rvq_stage_k(int s, const float* __restrict__ cb, float* __restrict__ outCodes, int writeCodes) {
    extern __shared__ float sm[];
    float* Bs = sm;                       // [2][32][256] codebook chunks (64KB)
    int*   codes_sm = (int*)(Bs + 2 * BK * BNC);   // [64]

    const int t = threadIdx.x, lane = t & 31, w = t >> 5;
    const long rowBase = (long)blockIdx.x * BM;

    const float* cbT = g_cbT + (size_t)s * DD * KK;
    const float* c2p = g_c2 + s * KK;
    const float* arow = g_res + (rowBase + w * 8) * DD + lane;   // + r*DD + dk*32

    const uint32_t BsA = (uint32_t)__cvta_generic_to_shared(Bs);

    // stage B chunk j into buffer j&1
    #define STAGE_B(j) do {                                                       \
        const int _dk = (j) & 7, _cc = (j) >> 3;                                  \
        const uint32_t _bb = BsA + (uint32_t)((j) & 1) * (BK * BNC * 4);          \
        _Pragma("unroll")                                                         \
        for (int k = 0; k < 8; k++) {                                             \
            int i4 = t + k * NTHREADS;                                            \
            int dd = i4 >> 6, c4 = i4 & 63;                                       \
            cpasync16(_bb + (uint32_t)(dd * BNC + c4 * 4) * 4,                    \
                      &cbT[(size_t)(_dk * BK + dd) * KK + _cc * BNC + c4 * 4]);   \
        }                                                                         \
        asm volatile("cp.async.commit_group;" ::: "memory");                      \
    } while (0)

    STAGE_B(0);

    // A registers for dk=0
    float Ac[8];
    #pragma unroll
    for (int r = 0; r < 8; r++) Ac[r] = arow[r * DD];

    float bestd[8];
    int   bestc[8];
    #pragma unroll
    for (int r = 0; r < 8; r++) { bestd[r] = 3.4e38f; bestc[r] = 0; }

    unsigned long long acc[8][4];   // [row][code-pair]: cp0/1 = codes l*4+{01,23}, cp2/3 = +128

    for (int j = 0; j < NITER; j++) {
        asm volatile("cp.async.wait_group 0;" ::: "memory");
        __syncthreads();
        if (j + 1 < NITER) STAGE_B(j + 1);   // safe: all warps finished compute(j-1) on this buffer

        const int cc = j >> 3, dk = j & 7;
        const float* bbuf = Bs + (j & 1) * (BK * BNC);

        if (dk == 0) {
            #pragma unroll
            for (int r = 0; r < 8; r++)
                #pragma unroll
                for (int cp = 0; cp < 4; cp++) acc[r][cp] = 0ull;
        }

        // prefetch next iteration's A registers (gmem, L2-hot, no sync needed)
        float An[8];
        if (j + 1 < NITER) {
            const float* ap = arow + ((j + 1) & 7) * BK;
            #pragma unroll
            for (int r = 0; r < 8; r++) An[r] = ap[r * DD];
        }

        #pragma unroll 8
        for (int dd = 0; dd < BK; dd++) {
            const ulonglong2 b0 = *(const ulonglong2*)&bbuf[dd * BNC + lane * 4];
            const ulonglong2 b1 = *(const ulonglong2*)&bbuf[dd * BNC + 128 + lane * 4];
            #pragma unroll
            for (int r = 0; r < 8; r++) {
                unsigned long long A2 = pack2(__shfl_sync(0xffffffffu, Ac[r], dd));
                ffma2(acc[r][0], A2, b0.x);
                ffma2(acc[r][1], A2, b0.y);
                ffma2(acc[r][2], A2, b1.x);
                ffma2(acc[r][3], A2, b1.y);
            }
        }

        if (dk == 7) {
            // dist = c2 - 2*dot ; codes ascend within thread -> plain lex argmin
            const float4 c2a = *(const float4*)&c2p[cc * BNC + lane * 4];
            const float4 c2b = *(const float4*)&c2p[cc * BNC + 128 + lane * 4];
            #pragma unroll
            for (int r = 0; r < 8; r++) {
                #pragma unroll
                for (int cp = 0; cp < 4; cp++) {
                    float2 dv = unpack2(acc[r][cp]);
                    int cg0 = cc * BNC + ((cp & 2) ? 128 : 0) + lane * 4 + 2 * (cp & 1);
                    float cva = (cp == 0) ? c2a.x : (cp == 1) ? c2a.z : (cp == 2) ? c2b.x : c2b.z;
                    float cvb = (cp == 0) ? c2a.y : (cp == 1) ? c2a.w : (cp == 2) ? c2b.y : c2b.w;
                    float d0 = fmaf(-2.f, dv.x, cva);
                    float d1 = fmaf(-2.f, dv.y, cvb);
                    if (d0 < bestd[r] || (d0 == bestd[r] && cg0 < bestc[r])) { bestd[r] = d0; bestc[r] = cg0; }
                    if (d1 < bestd[r] || (d1 == bestd[r] && cg0 + 1 < bestc[r])) { bestd[r] = d1; bestc[r] = cg0 + 1; }
                }
            }
        }

        if (j + 1 < NITER) {
            #pragma unroll
            for (int r = 0; r < 8; r++) Ac[r] = An[r];
        }
    }
    #undef STAGE_B

    // cross-lane argmin per row (all 32 lanes hold candidates for every row)
    #pragma unroll
    for (int r = 0; r < 8; r++) {
        float d = bestd[r]; int c = bestc[r];
        #pragma unroll
        for (int o = 16; o; o >>= 1) {
            float od = __shfl_xor_sync(0xffffffffu, d, o);
            int   oc = __shfl_xor_sync(0xffffffffu, c, o);
            if (od < d || (od == d && oc < c)) { d = od; c = oc; }
        }
        if (lane == 0) {
            codes_sm[w * 8 + r] = c;
            if (writeCodes) outCodes[(rowBase + w * 8 + r) * NQ + s] = (float)c;
        }
    }
    __syncthreads();

    // residual update (row-major): g_res[row] -= cb[code]
    for (int i = t; i < BM * (DD / 4); i += NTHREADS) {
        int r = i >> 6, d4 = i & 63;
        int code = codes_sm[r];
        size_t gi = (size_t)(rowBase + r) * DD + d4 * 4;
        float4 rv = *(const float4*)&g_res[gi];
        const float4 cv = *(const float4*)&cb[((size_t)s * KK + code) * DD + d4 * 4];
        rv.x -= cv.x; rv.y -= cv.y; rv.z -= cv.z; rv.w -= cv.w;
        *(float4*)&g_res[gi] = rv;
    }
}

// ---------------- launch ----------------
extern "C" void kernel_launch(void* const* d_in, const int* in_sizes, int n_in,
                              void* d_out, int out_size) {
    const float* x  = (const float*)d_in[0];
    const float* cb = (const float*)d_in[1];
    float* out = (float*)d_out;

    const long QE = (long)NTOT * DD;
    const long CE = (long)NTOT * NQ;

    int writeQ = (out_size >= QE) ? 1 : 0;
    float* outCodes = nullptr;
    int writeCodes = 0;
    if ((long)out_size >= QE + CE) { outCodes = out + QE; writeCodes = 1; }
    else if (!writeQ && (long)out_size >= CE) { outCodes = out; writeCodes = 1; }

    const int SMEM = 2 * BK * BNC * 4 + BM * 4;   // 64KB + 256B
    cudaFuncSetAttribute(rvq_stage_k, cudaFuncAttributeMaxDynamicSharedMemorySize, SMEM);

    float* cbT_ptr = nullptr;
    cudaGetSymbolAddress((void**)&cbT_ptr, g_cbT);

    dim3 tb(32, 8);
    // codebooks [NQ][K][D] -> [NQ][D][K]
    transpose_k<<<dim3(DD / 32, KK / 32, NQ), tb>>>(cb, cbT_ptr, KK, DD,
                                                    (long)KK * DD, (long)DD * KK);
    copy_res_k<<<(NTOT * DD / 4) / 256, 256>>>(x);
    c2_k<<<(NQ * KK * 32 + 255) / 256, 256>>>(cb);

    for (int s = 0; s < NQ; s++)
        rvq_stage_k<<<NTOT / BM, NTHREADS, SMEM>>>(s, cb, outCodes, writeCodes);

    if (writeQ)
        finalize_k<<<(NTOT * DD / 4) / 256, 256>>>(x, out);
}

// round 7
// speedup vs baseline: 1.2719x; 1.2719x over previous
#include <cuda_runtime.h>
#include <cstdint>

// Problem constants
#define DD   256
#define NQ   4
#define KK   1024
#define NTOT 131072

// Tiling
#define BM   64               // rows per CTA (8 warps x 8 rows)
#define BNC  256              // codes per chunk
#define BK   32               // d per staged chunk
#define NTHREADS 256
#define NITER 32              // 4 cc * 8 dk

// Scratch
__device__ float g_resT[(size_t)DD * NTOT];     // residual, transposed [d][n]
__device__ float g_cbT[(size_t)NQ * DD * KK];   // codebooks transposed [s][d][k]
__device__ float g_c2[NQ * KK];                 // ||c||^2 per code

// ---------------- packed f32x2 helpers ----------------
__device__ __forceinline__ unsigned long long pack2(float x) {
    unsigned long long r;
    unsigned int xi = __float_as_uint(x);
    asm("mov.b64 %0, {%1, %1};" : "=l"(r) : "r"(xi));
    return r;
}
__device__ __forceinline__ void ffma2(unsigned long long &acc,
                                      unsigned long long a,
                                      unsigned long long b) {
    asm("fma.rn.f32x2 %0, %1, %2, %0;" : "+l"(acc) : "l"(a), "l"(b));
}
__device__ __forceinline__ float2 unpack2(unsigned long long v) {
    unsigned int lo, hi;
    asm("mov.b64 {%0, %1}, %2;" : "=r"(lo), "=r"(hi) : "l"(v));
    return make_float2(__uint_as_float(lo), __uint_as_float(hi));
}
__device__ __forceinline__ void cpasync16(uint32_t s, const void* g) {
    asm volatile("cp.async.cg.shared.global [%0], [%1], 16;" :: "r"(s), "l"(g));
}

// ---------------- generic 32x32 tiled transpose: src[R][C] -> dst[C][R] ----------------
__global__ void transpose_k(const float* __restrict__ src, float* __restrict__ dst,
                            int R, int C, long srcBatch, long dstBatch) {
    __shared__ float tile[32][33];
    const float* s = src + (long)blockIdx.z * srcBatch;
    float*       d = dst + (long)blockIdx.z * dstBatch;
    int c0 = blockIdx.x * 32, r0 = blockIdx.y * 32;
    int tx = threadIdx.x, ty = threadIdx.y;           // 32 x 8
    #pragma unroll
    for (int i = 0; i < 32; i += 8)
        tile[ty + i][tx] = s[(long)(r0 + ty + i) * C + c0 + tx];
    __syncthreads();
    #pragma unroll
    for (int i = 0; i < 32; i += 8)
        d[(long)(c0 + ty + i) * R + r0 + tx] = tile[tx][ty + i];
}

// ---------------- ||c||^2 per code ----------------
__global__ void c2_k(const float* __restrict__ cb) {
    int w = (blockIdx.x * blockDim.x + threadIdx.x) >> 5;
    int lane = threadIdx.x & 31;
    if (w >= NQ * KK) return;
    const float* row = cb + (long)w * DD;
    float s = 0.f;
    #pragma unroll
    for (int j = lane; j < DD; j += 32) { float v = row[j]; s = fmaf(v, v, s); }
    #pragma unroll
    for (int o = 16; o; o >>= 1) s += __shfl_xor_sync(0xffffffffu, s, o);
    if (lane == 0) g_c2[w] = s;
}

// ---------------- finalize: quantised[n][d] = x[n][d] - resT[d][n] ----------------
__global__ void finalize_k(const float* __restrict__ x, float* __restrict__ out) {
    __shared__ float tile[32][33];
    int n0 = blockIdx.x * 32, d0 = blockIdx.y * 32;
    int tx = threadIdx.x, ty = threadIdx.y;   // 32 x 8
    #pragma unroll
    for (int i = 0; i < 32; i += 8)
        tile[ty + i][tx] = g_resT[(size_t)(d0 + ty + i) * NTOT + n0 + tx];
    __syncthreads();
    #pragma unroll
    for (int i = 0; i < 32; i += 8) {
        long n = n0 + ty + i;
        int  d = d0 + tx;
        out[n * DD + d] = x[n * DD + d] - tile[tx][ty + i];
    }
}

// ---------------- main per-stage kernel ----------------
// 8 warps. Warp w owns rows w*8..w*8+7 and ALL 256 codes of each chunk.
// Lane l owns codes {cc*256 + l*4 + q} and {cc*256 + 128 + l*4 + q}, q=0..3.
// A comes from a small smem tile [dd][64 rows] via broadcast LDS.128 (4 wf/dd);
// B via dense LDS.128 (8 wf/dd). Total 12 wf/dd/warp vs 16 fma-issue-slots -> fma-bound.
__global__ void __launch_bounds__(NTHREADS, 2)
rvq_stage_k(int s, const float* __restrict__ cb, float* __restrict__ outCodes, int writeCodes) {
    extern __shared__ float sm[];
    float* As = sm;                                // [2][32][64]   8KB each
    float* Bs = As + 2 * BK * BM;                  // [2][32][256]  32KB each
    int*   codes_sm = (int*)(Bs + 2 * BK * BNC);   // [64]

    const int t = threadIdx.x, lane = t & 31, w = t >> 5;
    const long rowBase = (long)blockIdx.x * BM;

    const float* cbT = g_cbT + (size_t)s * DD * KK;
    const float* c2p = g_c2 + s * KK;

    const uint32_t AsA = (uint32_t)__cvta_generic_to_shared(As);
    const uint32_t BsA = (uint32_t)__cvta_generic_to_shared(Bs);

    // stage chunk j (A residual + B codebook) into buffer j&1
    #define STAGE(j) do {                                                         \
        const int _dk = (j) & 7, _cc = (j) >> 3;                                  \
        const uint32_t _ab = AsA + (uint32_t)((j) & 1) * (BK * BM * 4);           \
        const uint32_t _bb = BsA + (uint32_t)((j) & 1) * (BK * BNC * 4);          \
        _Pragma("unroll")                                                         \
        for (int k = 0; k < 2; k++) {                                             \
            int i4 = t + k * NTHREADS;            /* [0,512): A 32dd x 16 u16B */ \
            int dd = i4 >> 4, r4 = i4 & 15;                                       \
            cpasync16(_ab + (uint32_t)(dd * BM + r4 * 4) * 4,                     \
                      &g_resT[(size_t)(_dk * BK + dd) * NTOT + rowBase + r4 * 4]);\
        }                                                                         \
        _Pragma("unroll")                                                         \
        for (int k = 0; k < 8; k++) {                                             \
            int i4 = t + k * NTHREADS;            /* [0,2048): B 32dd x 64 u16B */\
            int dd = i4 >> 6, c4 = i4 & 63;                                       \
            cpasync16(_bb + (uint32_t)(dd * BNC + c4 * 4) * 4,                    \
                      &cbT[(size_t)(_dk * BK + dd) * KK + _cc * BNC + c4 * 4]);   \
        }                                                                         \
        asm volatile("cp.async.commit_group;" ::: "memory");                      \
    } while (0)

    STAGE(0);

    float bestd[8];
    int   bestc[8];
    #pragma unroll
    for (int r = 0; r < 8; r++) { bestd[r] = 3.4e38f; bestc[r] = 0; }

    unsigned long long acc[8][4];   // [row][code-pair]: cp0/1 = lane*4+{01,23}, cp2/3 = +128

    for (int j = 0; j < NITER; j++) {
        asm volatile("cp.async.wait_group 0;" ::: "memory");
        __syncthreads();
        // prefetch j+1 into buffer (j+1)&1: that buffer was last read by compute(j-1),
        // complete in all warps because every warp passed the barrier above.
        if (j + 1 < NITER) STAGE(j + 1);

        const int cc = j >> 3, dk = j & 7;
        const float* abuf = As + (j & 1) * (BK * BM);
        const float* bbuf = Bs + (j & 1) * (BK * BNC);

        if (dk == 0) {
            #pragma unroll
            for (int r = 0; r < 8; r++)
                #pragma unroll
                for (int cp = 0; cp < 4; cp++) acc[r][cp] = 0ull;
        }

        #pragma unroll 8
        for (int dd = 0; dd < BK; dd++) {
            const float4 a0 = *(const float4*)&abuf[dd * BM + w * 8];       // broadcast
            const float4 a1 = *(const float4*)&abuf[dd * BM + w * 8 + 4];   // broadcast
            const ulonglong2 b0 = *(const ulonglong2*)&bbuf[dd * BNC + lane * 4];        // dense
            const ulonglong2 b1 = *(const ulonglong2*)&bbuf[dd * BNC + 128 + lane * 4];  // dense
            unsigned long long A[8];
            A[0] = pack2(a0.x); A[1] = pack2(a0.y); A[2] = pack2(a0.z); A[3] = pack2(a0.w);
            A[4] = pack2(a1.x); A[5] = pack2(a1.y); A[6] = pack2(a1.z); A[7] = pack2(a1.w);
            #pragma unroll
            for (int r = 0; r < 8; r++) {
                ffma2(acc[r][0], A[r], b0.x);
                ffma2(acc[r][1], A[r], b0.y);
                ffma2(acc[r][2], A[r], b1.x);
                ffma2(acc[r][3], A[r], b1.y);
            }
        }

        if (dk == 7) {
            // dist = c2 - 2*dot ; codes ascend within each thread -> lexicographic argmin
            const float4 c2a = *(const float4*)&c2p[cc * BNC + lane * 4];
            const float4 c2b = *(const float4*)&c2p[cc * BNC + 128 + lane * 4];
            #pragma unroll
            for (int r = 0; r < 8; r++) {
                #pragma unroll
                for (int cp = 0; cp < 4; cp++) {
                    float2 dv = unpack2(acc[r][cp]);
                    int cg0 = cc * BNC + ((cp & 2) ? 128 : 0) + lane * 4 + 2 * (cp & 1);
                    float cva = (cp == 0) ? c2a.x : (cp == 1) ? c2a.z : (cp == 2) ? c2b.x : c2b.z;
                    float cvb = (cp == 0) ? c2a.y : (cp == 1) ? c2a.w : (cp == 2) ? c2b.y : c2b.w;
                    float d0 = fmaf(-2.f, dv.x, cva);
                    float d1 = fmaf(-2.f, dv.y, cvb);
                    if (d0 < bestd[r] || (d0 == bestd[r] && cg0 < bestc[r])) { bestd[r] = d0; bestc[r] = cg0; }
                    if (d1 < bestd[r] || (d1 == bestd[r] && cg0 + 1 < bestc[r])) { bestd[r] = d1; bestc[r] = cg0 + 1; }
                }
            }
        }
    }
    #undef STAGE

    // cross-lane argmin per row (lanes hold disjoint code subsets)
    #pragma unroll
    for (int r = 0; r < 8; r++) {
        float d = bestd[r]; int c = bestc[r];
        #pragma unroll
        for (int o = 16; o; o >>= 1) {
            float od = __shfl_xor_sync(0xffffffffu, d, o);
            int   oc = __shfl_xor_sync(0xffffffffu, c, o);
            if (od < d || (od == d && oc < c)) { d = od; c = oc; }
        }
        if (lane == 0) {
            codes_sm[w * 8 + r] = c;
            if (writeCodes) outCodes[(rowBase + w * 8 + r) * NQ + s] = (float)c;
        }
    }
    __syncthreads();

    // residual update: g_resT[d][rowBase+r] -= cbT[d][code_r]
    for (int i = t; i < DD * BM; i += NTHREADS) {
        int d = i >> 6, r = i & 63;
        int code = codes_sm[r];
        size_t gi = (size_t)d * NTOT + rowBase + r;
        g_resT[gi] = g_resT[gi] - cbT[(size_t)d * KK + code];
    }
}

// ---------------- launch ----------------
extern "C" void kernel_launch(void* const* d_in, const int* in_sizes, int n_in,
                              void* d_out, int out_size) {
    const float* x  = (const float*)d_in[0];
    const float* cb = (const float*)d_in[1];
    float* out = (float*)d_out;

    const long QE = (long)NTOT * DD;
    const long CE = (long)NTOT * NQ;

    int writeQ = (out_size >= QE) ? 1 : 0;
    float* outCodes = nullptr;
    int writeCodes = 0;
    if ((long)out_size >= QE + CE) { outCodes = out + QE; writeCodes = 1; }
    else if (!writeQ && (long)out_size >= CE) { outCodes = out; writeCodes = 1; }

    const int SMEM = (2 * BK * BM + 2 * BK * BNC) * 4 + BM * 4;   // 80.25 KB
    cudaFuncSetAttribute(rvq_stage_k, cudaFuncAttributeMaxDynamicSharedMemorySize, SMEM);

    float* cbT_ptr = nullptr;
    cudaGetSymbolAddress((void**)&cbT_ptr, g_cbT);
    float* resT_ptr = nullptr;
    cudaGetSymbolAddress((void**)&resT_ptr, g_resT);

    dim3 tb(32, 8);
    // codebooks [NQ][K][D] -> [NQ][D][K]
    transpose_k<<<dim3(DD / 32, KK / 32, NQ), tb>>>(cb, cbT_ptr, KK, DD,
                                                    (long)KK * DD, (long)DD * KK);
    // x [N][D] -> resT [D][N]
    transpose_k<<<dim3(DD / 32, NTOT / 32, 1), tb>>>(x, resT_ptr, NTOT, DD, 0, 0);
    c2_k<<<(NQ * KK * 32 + 255) / 256, 256>>>(cb);

    for (int s = 0; s < NQ; s++)
        rvq_stage_k<<<NTOT / BM, NTHREADS, SMEM>>>(s, cb, outCodes, writeCodes);

    if (writeQ)
        finalize_k<<<dim3(NTOT / 32, DD / 32), tb>>>(x, out);
}

// round 9
// speedup vs baseline: 1.3508x; 1.0621x over previous
#include <cuda_runtime.h>
#include <cstdint>

// Problem constants
#define DD   256
#define NQ   4
#define KK   1024
#define NTOT 131072

// Tiling
#define BM   64               // rows per CTA (8 warps x 8 rows), resident in smem
#define BNC  256              // codes per chunk
#define BK   16               // d per staged B chunk
#define NTHREADS 256
#define NITER_T  256          // 4 stages * 4 cc * 16 dk

// Scratch (read-only after prep)
__device__ float g_xT[(size_t)DD * NTOT];       // x transposed [d][n]
__device__ float g_cbT[(size_t)NQ * DD * KK];   // codebooks transposed [s][d][k]
__device__ float g_c2[NQ * KK];                 // ||c||^2 per code

// ---------------- packed f32x2 helpers ----------------
__device__ __forceinline__ unsigned long long pack2(float x) {
    unsigned long long r;
    unsigned int xi = __float_as_uint(x);
    asm("mov.b64 %0, {%1, %1};" : "=l"(r) : "r"(xi));
    return r;
}
__device__ __forceinline__ void ffma2(unsigned long long &acc,
                                      unsigned long long a,
                                      unsigned long long b) {
    asm("fma.rn.f32x2 %0, %1, %2, %0;" : "+l"(acc) : "l"(a), "l"(b));
}
__device__ __forceinline__ float2 unpack2(unsigned long long v) {
    unsigned int lo, hi;
    asm("mov.b64 {%0, %1}, %2;" : "=r"(lo), "=r"(hi) : "l"(v));
    return make_float2(__uint_as_float(lo), __uint_as_float(hi));
}
__device__ __forceinline__ void cpasync16(uint32_t s, const void* g) {
    asm volatile("cp.async.cg.shared.global [%0], [%1], 16;" :: "r"(s), "l"(g));
}

// ---------------- generic 32x32 tiled transpose: src[R][C] -> dst[C][R] ----------------
__global__ void transpose_k(const float* __restrict__ src, float* __restrict__ dst,
                            int R, int C, long srcBatch, long dstBatch) {
    __shared__ float tile[32][33];
    const float* s = src + (long)blockIdx.z * srcBatch;
    float*       d = dst + (long)blockIdx.z * dstBatch;
    int c0 = blockIdx.x * 32, r0 = blockIdx.y * 32;
    int tx = threadIdx.x, ty = threadIdx.y;           // 32 x 8
    #pragma unroll
    for (int i = 0; i < 32; i += 8)
        tile[ty + i][tx] = s[(long)(r0 + ty + i) * C + c0 + tx];
    __syncthreads();
    #pragma unroll
    for (int i = 0; i < 32; i += 8)
        d[(long)(c0 + ty + i) * R + r0 + tx] = tile[tx][ty + i];
}

// ---------------- ||c||^2 per code ----------------
__global__ void c2_k(const float* __restrict__ cb) {
    int w = (blockIdx.x * blockDim.x + threadIdx.x) >> 5;
    int lane = threadIdx.x & 31;
    if (w >= NQ * KK) return;
    const float* row = cb + (long)w * DD;
    float s = 0.f;
    #pragma unroll
    for (int j = lane; j < DD; j += 32) { float v = row[j]; s = fmaf(v, v, s); }
    #pragma unroll
    for (int o = 16; o; o >>= 1) s += __shfl_xor_sync(0xffffffffu, s, o);
    if (lane == 0) g_c2[w] = s;
}

// ---------------- fused all-stages kernel ----------------
// Residual tile [256 d][64 rows] lives in smem for the whole kernel.
// 8 warps; warp w owns rows w*8..w*8+7, all 256 codes of each chunk.
// Lane l owns codes {cc*256 + l*4 + q} and {cc*256 + 128 + l*4 + q}, q=0..3.
// Pipeline (R7-proven ordering): loop head = wait_group 0 -> __syncthreads ->
// issue STAGE_B(J+1) into buffer (J+1)&1, which compute(J-1) last read and every
// warp has finished with (all passed the barrier).
__global__ void __launch_bounds__(NTHREADS, 2)
rvq_fused_k(const float* __restrict__ cb, float* __restrict__ outQ, int writeQ,
            float* __restrict__ outCodes, int writeCodes) {
    extern __shared__ float sm[];
    float* Rs = sm;                           // [256][64]  64KB resident residual
    float* Bs = Rs + DD * BM;                 // [2][16][256]  2x16KB B chunks
    int*   codes_all = (int*)(Bs + 2 * BK * BNC);   // [4][64]

    const int t = threadIdx.x, lane = t & 31, w = t >> 5;
    const long rowBase = (long)blockIdx.x * BM;

    const uint32_t RsA = (uint32_t)__cvta_generic_to_shared(Rs);
    const uint32_t BsA = (uint32_t)__cvta_generic_to_shared(Bs);

    // stage B chunk for linear iteration JN into buffer JN&1
    #define STAGE_B(JN) do {                                                       \
        const int _s = (JN) >> 6, _cc = ((JN) >> 4) & 3, _dk = (JN) & 15;          \
        const uint32_t _bb = BsA + (uint32_t)((JN) & 1) * (BK * BNC * 4);          \
        const float* _src = g_cbT + ((size_t)_s * DD + _dk * BK) * KK + _cc * BNC; \
        _Pragma("unroll")                                                          \
        for (int k = 0; k < 4; k++) {                                              \
            int i4 = t + k * NTHREADS;            /* [0,1024): 16dd x 64 u16B */   \
            int dd = i4 >> 6, c4 = i4 & 63;                                        \
            cpasync16(_bb + (uint32_t)(dd * BNC + c4 * 4) * 4,                     \
                      &_src[(size_t)dd * KK + c4 * 4]);                            \
        }                                                                          \
        asm volatile("cp.async.commit_group;" ::: "memory");                       \
    } while (0)

    // group 0: resident residual tile (from transposed x) + B chunk 0
    #pragma unroll
    for (int k = 0; k < 16; k++) {
        int i4 = t + k * NTHREADS;                // [0,4096): 256d x 16 u16B
        int d = i4 >> 4, seg = i4 & 15;
        cpasync16(RsA + (uint32_t)(d * BM + seg * 4) * 4,
                  &g_xT[(size_t)d * NTOT + rowBase + seg * 4]);
    }
    STAGE_B(0);

    float bestd[8];
    int   bestc[8];
    #pragma unroll
    for (int r = 0; r < 8; r++) { bestd[r] = 3.4e38f; bestc[r] = 0; }

    unsigned long long acc[8][4];   // [row][code-pair]: cp0/1 = lane*4+{01,23}, cp2/3 = +128

    for (int J = 0; J < NITER_T; J++) {
        asm volatile("cp.async.wait_group 0;" ::: "memory");
        __syncthreads();
        // safe prefetch point: all warps completed compute(J-1), the last reader
        // of buffer (J+1)&1.
        if (J + 1 < NITER_T) STAGE_B(J + 1);

        const int s = J >> 6, cc = (J >> 4) & 3, dk = J & 15;
        const float* bbuf = Bs + (J & 1) * (BK * BNC);

        if (dk == 0) {
            #pragma unroll
            for (int r = 0; r < 8; r++)
                #pragma unroll
                for (int cp = 0; cp < 4; cp++) acc[r][cp] = 0ull;
        }

        #pragma unroll
        for (int dd = 0; dd < BK; dd++) {
            const float4 a0 = *(const float4*)&Rs[(dk * BK + dd) * BM + w * 8];       // broadcast
            const float4 a1 = *(const float4*)&Rs[(dk * BK + dd) * BM + w * 8 + 4];   // broadcast
            const ulonglong2 b0 = *(const ulonglong2*)&bbuf[dd * BNC + lane * 4];        // dense
            const ulonglong2 b1 = *(const ulonglong2*)&bbuf[dd * BNC + 128 + lane * 4];  // dense
            unsigned long long A[8];
            A[0] = pack2(a0.x); A[1] = pack2(a0.y); A[2] = pack2(a0.z); A[3] = pack2(a0.w);
            A[4] = pack2(a1.x); A[5] = pack2(a1.y); A[6] = pack2(a1.z); A[7] = pack2(a1.w);
            #pragma unroll
            for (int r = 0; r < 8; r++) {
                ffma2(acc[r][0], A[r], b0.x);
                ffma2(acc[r][1], A[r], b0.y);
                ffma2(acc[r][2], A[r], b1.x);
                ffma2(acc[r][3], A[r], b1.y);
            }
        }

        if (dk == 15) {
            // dist = c2 - 2*dot ; codes ascend within each thread -> lexicographic argmin
            const float* c2p = g_c2 + s * KK;
            const float4 c2a = *(const float4*)&c2p[cc * BNC + lane * 4];
            const float4 c2b = *(const float4*)&c2p[cc * BNC + 128 + lane * 4];
            #pragma unroll
            for (int r = 0; r < 8; r++) {
                #pragma unroll
                for (int cp = 0; cp < 4; cp++) {
                    float2 dv = unpack2(acc[r][cp]);
                    int cg0 = cc * BNC + ((cp & 2) ? 128 : 0) + lane * 4 + 2 * (cp & 1);
                    float cva = (cp == 0) ? c2a.x : (cp == 1) ? c2a.z : (cp == 2) ? c2b.x : c2b.z;
                    float cvb = (cp == 0) ? c2a.y : (cp == 1) ? c2a.w : (cp == 2) ? c2b.y : c2b.w;
                    float d0 = fmaf(-2.f, dv.x, cva);
                    float d1 = fmaf(-2.f, dv.y, cvb);
                    if (d0 < bestd[r] || (d0 == bestd[r] && cg0 < bestc[r])) { bestd[r] = d0; bestc[r] = cg0; }
                    if (d1 < bestd[r] || (d1 == bestd[r] && cg0 + 1 < bestc[r])) { bestd[r] = d1; bestc[r] = cg0 + 1; }
                }
            }
        }

        // stage-end: argmin merge + in-smem residual update
        if ((J & 63) == 63) {
            #pragma unroll
            for (int r = 0; r < 8; r++) {
                float d = bestd[r]; int c = bestc[r];
                #pragma unroll
                for (int o = 16; o; o >>= 1) {
                    float od = __shfl_xor_sync(0xffffffffu, d, o);
                    int   oc = __shfl_xor_sync(0xffffffffu, c, o);
                    if (od < d || (od == d && oc < c)) { d = od; c = oc; }
                }
                if (lane == 0) {
                    codes_all[s * BM + w * 8 + r] = c;
                    if (writeCodes) outCodes[(rowBase + w * 8 + r) * NQ + s] = (float)c;
                }
                bestd[r] = 3.4e38f; bestc[r] = 0;
            }
            __syncthreads();            // codes_all visible to all
            if (s < NQ - 1) {
                // Rs[d][r] -= cb_s[code_r][d]; thread: r = t&63, d-group = t>>6
                const int r = t & 63, dg = t >> 6;
                const int code = codes_all[s * BM + r];
                const float* crow = cb + ((size_t)s * KK + code) * DD + dg * 64;
                #pragma unroll 8
                for (int db = 0; db < 64; db++) {
                    Rs[(dg * 64 + db) * BM + r] -= crow[db];
                }
            }
            // the next loop-head __syncthreads orders this update before stage s+1 compute
        }
    }
    #undef STAGE_B

    // quantised output: out[row] = ((cb0[c0] + cb1[c1]) + cb2[c2]) + cb3[c3]
    // (matches the reference scan's sequential total accumulation order)
    if (writeQ) {
        #pragma unroll
        for (int rr = 0; rr < 8; rr++) {
            int row = w * 8 + rr;
            int c0 = codes_all[row];
            int c1 = codes_all[BM + row];
            int c2 = codes_all[2 * BM + row];
            int c3 = codes_all[3 * BM + row];
            const float4* q0 = (const float4*)(cb + (size_t)c0 * DD);
            const float4* q1 = (const float4*)(cb + ((size_t)KK + c1) * DD);
            const float4* q2 = (const float4*)(cb + ((size_t)2 * KK + c2) * DD);
            const float4* q3 = (const float4*)(cb + ((size_t)3 * KK + c3) * DD);
            float4* orow = (float4*)(outQ + (rowBase + row) * DD);
            #pragma unroll
            for (int dq = 0; dq < 2; dq++) {
                int idx = lane + dq * 32;
                float4 v0 = q0[idx], v1 = q1[idx], v2 = q2[idx], v3 = q3[idx];
                float4 o;
                o.x = ((v0.x + v1.x) + v2.x) + v3.x;
                o.y = ((v0.y + v1.y) + v2.y) + v3.y;
                o.z = ((v0.z + v1.z) + v2.z) + v3.z;
                o.w = ((v0.w + v1.w) + v2.w) + v3.w;
                orow[idx] = o;
            }
        }
    }
}

// ---------------- launch ----------------
extern "C" void kernel_launch(void* const* d_in, const int* in_sizes, int n_in,
                              void* d_out, int out_size) {
    const float* x  = (const float*)d_in[0];
    const float* cb = (const float*)d_in[1];
    float* out = (float*)d_out;

    const long QE = (long)NTOT * DD;
    const long CE = (long)NTOT * NQ;

    int writeQ = (out_size >= QE) ? 1 : 0;
    float* outCodes = nullptr;
    int writeCodes = 0;
    if ((long)out_size >= QE + CE) { outCodes = out + QE; writeCodes = 1; }
    else if (!writeQ && (long)out_size >= CE) { outCodes = out; writeCodes = 1; }

    const int SMEM = (DD * BM + 2 * BK * BNC) * 4 + NQ * BM * 4;   // 99328 B
    cudaFuncSetAttribute(rvq_fused_k, cudaFuncAttributeMaxDynamicSharedMemorySize, SMEM);

    float* cbT_ptr = nullptr;
    cudaGetSymbolAddress((void**)&cbT_ptr, g_cbT);
    float* xT_ptr = nullptr;
    cudaGetSymbolAddress((void**)&xT_ptr, g_xT);

    dim3 tb(32, 8);
    // codebooks [NQ][K][D] -> [NQ][D][K]
    transpose_k<<<dim3(DD / 32, KK / 32, NQ), tb>>>(cb, cbT_ptr, KK, DD,
                                                    (long)KK * DD, (long)DD * KK);
    // x [N][D] -> xT [D][N]
    transpose_k<<<dim3(DD / 32, NTOT / 32, 1), tb>>>(x, xT_ptr, NTOT, DD, 0, 0);
    c2_k<<<(NQ * KK * 32 + 255) / 256, 256>>>(cb);

    rvq_fused_k<<<NTOT / BM, NTHREADS, SMEM>>>(cb, out, writeQ, outCodes, writeCodes);
}

// round 10
// speedup vs baseline: 1.4115x; 1.0450x over previous
#include <cuda_runtime.h>
#include <cstdint>

// Problem constants
#define DD   256
#define NQ   4
#define KK   1024
#define NTOT 131072

// Tiling
#define BM   64               // rows per CTA (8 warps x 8 rows), resident in smem
#define BNC  256              // codes per chunk
#define BK   16               // d per staged B chunk
#define NTHREADS 256
#define NITER_T  256          // 4 stages * 4 cc * 16 dk

// Scratch (read-only after prep)
__device__ float g_cbT[(size_t)NQ * DD * KK];   // codebooks transposed [s][d][k]
__device__ float g_c2[NQ * KK];                 // ||c||^2 per code

// ---------------- packed f32x2 helpers ----------------
__device__ __forceinline__ unsigned long long pack2(float x) {
    unsigned long long r;
    unsigned int xi = __float_as_uint(x);
    asm("mov.b64 %0, {%1, %1};" : "=l"(r) : "r"(xi));
    return r;
}
__device__ __forceinline__ void ffma2(unsigned long long &acc,
                                      unsigned long long a,
                                      unsigned long long b) {
    asm("fma.rn.f32x2 %0, %1, %2, %0;" : "+l"(acc) : "l"(a), "l"(b));
}
__device__ __forceinline__ float2 unpack2(unsigned long long v) {
    unsigned int lo, hi;
    asm("mov.b64 {%0, %1}, %2;" : "=r"(lo), "=r"(hi) : "l"(v));
    return make_float2(__uint_as_float(lo), __uint_as_float(hi));
}
__device__ __forceinline__ void cpasync16(uint32_t s, const void* g) {
    asm volatile("cp.async.cg.shared.global [%0], [%1], 16;" :: "r"(s), "l"(g));
}

// ---------------- codebook transpose [NQ][K][D] -> [NQ][D][K] ----------------
__global__ void transpose_k(const float* __restrict__ src, float* __restrict__ dst,
                            int R, int C, long srcBatch, long dstBatch) {
    __shared__ float tile[32][33];
    const float* s = src + (long)blockIdx.z * srcBatch;
    float*       d = dst + (long)blockIdx.z * dstBatch;
    int c0 = blockIdx.x * 32, r0 = blockIdx.y * 32;
    int tx = threadIdx.x, ty = threadIdx.y;           // 32 x 8
    #pragma unroll
    for (int i = 0; i < 32; i += 8)
        tile[ty + i][tx] = s[(long)(r0 + ty + i) * C + c0 + tx];
    __syncthreads();
    #pragma unroll
    for (int i = 0; i < 32; i += 8)
        d[(long)(c0 + ty + i) * R + r0 + tx] = tile[tx][ty + i];
}

// ---------------- ||c||^2 per code ----------------
__global__ void c2_k(const float* __restrict__ cb) {
    int w = (blockIdx.x * blockDim.x + threadIdx.x) >> 5;
    int lane = threadIdx.x & 31;
    if (w >= NQ * KK) return;
    const float* row = cb + (long)w * DD;
    float s = 0.f;
    #pragma unroll
    for (int j = lane; j < DD; j += 32) { float v = row[j]; s = fmaf(v, v, s); }
    #pragma unroll
    for (int o = 16; o; o >>= 1) s += __shfl_xor_sync(0xffffffffu, s, o);
    if (lane == 0) g_c2[w] = s;
}

// ---------------- fused all-stages kernel ----------------
// Residual tile [256 d][64 rows] lives in smem for the whole kernel.
// 8 warps; warp w owns rows w*8..w*8+7, all 256 codes of each chunk.
// Lane l owns codes {cc*256 + l*4 + q} and {cc*256 + 128 + l*4 + q}, q=0..3.
__global__ void __launch_bounds__(NTHREADS, 2)
rvq_fused_k(const float* __restrict__ x, const float* __restrict__ cb,
            float* __restrict__ outQ, int writeQ,
            float* __restrict__ outCodes, int writeCodes) {
    extern __shared__ float sm[];
    float* Rs = sm;                           // [256][64]  64KB resident residual
    float* Bs = Rs + DD * BM;                 // [2][16][256]  2x16KB B chunks
    int*   codes_all = (int*)(Bs + 2 * BK * BNC);   // [4][64]

    const int t = threadIdx.x, lane = t & 31, w = t >> 5;
    const long rowBase = (long)blockIdx.x * BM;

    const uint32_t BsA = (uint32_t)__cvta_generic_to_shared(Bs);

    // stage B chunk for linear iteration JN into buffer JN&1
    #define STAGE_B(JN) do {                                                       \
        const int _s = (JN) >> 6, _cc = ((JN) >> 4) & 3, _dk = (JN) & 15;          \
        const uint32_t _bb = BsA + (uint32_t)((JN) & 1) * (BK * BNC * 4);          \
        const float* _src = g_cbT + ((size_t)_s * DD + _dk * BK) * KK + _cc * BNC; \
        _Pragma("unroll")                                                          \
        for (int k = 0; k < 4; k++) {                                              \
            int i4 = t + k * NTHREADS;            /* [0,1024): 16dd x 64 u16B */   \
            int dd = i4 >> 6, c4 = i4 & 63;                                        \
            cpasync16(_bb + (uint32_t)(dd * BNC + c4 * 4) * 4,                     \
                      &_src[(size_t)dd * KK + c4 * 4]);                            \
        }                                                                          \
        asm volatile("cp.async.commit_group;" ::: "memory");                       \
    } while (0)

    STAGE_B(0);

    // residual tile: direct from row-major x with in-kernel transpose.
    // thread: row = t&63, d-group = t>>6 (64 dims). LDG.128 sectored per thread;
    // STS conflict-free (lanes -> distinct rows -> distinct banks).
    {
        const int r = t & 63, dg = t >> 6;
        const float* xrow = x + (rowBase + r) * DD + dg * 64;
        #pragma unroll
        for (int i = 0; i < 16; i++) {
            float4 v = *(const float4*)&xrow[i * 4];
            Rs[(dg * 64 + i * 4 + 0) * BM + r] = v.x;
            Rs[(dg * 64 + i * 4 + 1) * BM + r] = v.y;
            Rs[(dg * 64 + i * 4 + 2) * BM + r] = v.z;
            Rs[(dg * 64 + i * 4 + 3) * BM + r] = v.w;
        }
    }

    float bestd[8];
    int   bestc[8];
    #pragma unroll
    for (int r = 0; r < 8; r++) { bestd[r] = 3.4e38f; bestc[r] = 0; }

    unsigned long long acc[8][4];   // [row][code-pair]: cp0/1 = lane*4+{01,23}, cp2/3 = +128

    for (int J = 0; J < NITER_T; J++) {
        asm volatile("cp.async.wait_group 0;" ::: "memory");
        __syncthreads();
        // safe prefetch point: all warps completed compute(J-1), the last reader
        // of buffer (J+1)&1.
        if (J + 1 < NITER_T) STAGE_B(J + 1);

        const int s = J >> 6, cc = (J >> 4) & 3, dk = J & 15;
        const float* bbuf = Bs + (J & 1) * (BK * BNC);

        if (dk == 0) {
            #pragma unroll
            for (int r = 0; r < 8; r++)
                #pragma unroll
                for (int cp = 0; cp < 4; cp++) acc[r][cp] = 0ull;
        }

        #pragma unroll
        for (int dd = 0; dd < BK; dd++) {
            const float4 a0 = *(const float4*)&Rs[(dk * BK + dd) * BM + w * 8];       // broadcast
            const float4 a1 = *(const float4*)&Rs[(dk * BK + dd) * BM + w * 8 + 4];   // broadcast
            const ulonglong2 b0 = *(const ulonglong2*)&bbuf[dd * BNC + lane * 4];        // dense
            const ulonglong2 b1 = *(const ulonglong2*)&bbuf[dd * BNC + 128 + lane * 4];  // dense
            unsigned long long A[8];
            A[0] = pack2(a0.x); A[1] = pack2(a0.y); A[2] = pack2(a0.z); A[3] = pack2(a0.w);
            A[4] = pack2(a1.x); A[5] = pack2(a1.y); A[6] = pack2(a1.z); A[7] = pack2(a1.w);
            #pragma unroll
            for (int r = 0; r < 8; r++) {
                ffma2(acc[r][0], A[r], b0.x);
                ffma2(acc[r][1], A[r], b0.y);
                ffma2(acc[r][2], A[r], b1.x);
                ffma2(acc[r][3], A[r], b1.y);
            }
        }

        if (dk == 15) {
            // dist = c2 - 2*dot ; codes ascend within each thread -> lexicographic argmin
            const float* c2p = g_c2 + s * KK;
            const float4 c2a = *(const float4*)&c2p[cc * BNC + lane * 4];
            const float4 c2b = *(const float4*)&c2p[cc * BNC + 128 + lane * 4];
            #pragma unroll
            for (int r = 0; r < 8; r++) {
                #pragma unroll
                for (int cp = 0; cp < 4; cp++) {
                    float2 dv = unpack2(acc[r][cp]);
                    int cg0 = cc * BNC + ((cp & 2) ? 128 : 0) + lane * 4 + 2 * (cp & 1);
                    float cva = (cp == 0) ? c2a.x : (cp == 1) ? c2a.z : (cp == 2) ? c2b.x : c2b.z;
                    float cvb = (cp == 0) ? c2a.y : (cp == 1) ? c2a.w : (cp == 2) ? c2b.y : c2b.w;
                    float d0 = fmaf(-2.f, dv.x, cva);
                    float d1 = fmaf(-2.f, dv.y, cvb);
                    if (d0 < bestd[r] || (d0 == bestd[r] && cg0 < bestc[r])) { bestd[r] = d0; bestc[r] = cg0; }
                    if (d1 < bestd[r] || (d1 == bestd[r] && cg0 + 1 < bestc[r])) { bestd[r] = d1; bestc[r] = cg0 + 1; }
                }
            }
        }

        // stage-end: argmin merge + in-smem residual update
        if ((J & 63) == 63) {
            #pragma unroll
            for (int r = 0; r < 8; r++) {
                float d = bestd[r]; int c = bestc[r];
                #pragma unroll
                for (int o = 16; o; o >>= 1) {
                    float od = __shfl_xor_sync(0xffffffffu, d, o);
                    int   oc = __shfl_xor_sync(0xffffffffu, c, o);
                    if (od < d || (od == d && oc < c)) { d = od; c = oc; }
                }
                if (lane == 0) {
                    codes_all[s * BM + w * 8 + r] = c;
                    if (writeCodes) outCodes[(rowBase + w * 8 + r) * NQ + s] = (float)c;
                }
                bestd[r] = 3.4e38f; bestc[r] = 0;
            }
            __syncthreads();            // codes_all visible to all
            if (s < NQ - 1) {
                // Rs[d][r] -= cb_s[code_r][d]; thread: r = t&63, d-group = t>>6.
                // float4 gather (16 LDG.128) + conflict-free scalar smem RMW.
                const int r = t & 63, dg = t >> 6;
                const int code = codes_all[s * BM + r];
                const float* crow = cb + ((size_t)s * KK + code) * DD + dg * 64;
                #pragma unroll
                for (int i = 0; i < 16; i++) {
                    float4 v = *(const float4*)&crow[i * 4];
                    Rs[(dg * 64 + i * 4 + 0) * BM + r] -= v.x;
                    Rs[(dg * 64 + i * 4 + 1) * BM + r] -= v.y;
                    Rs[(dg * 64 + i * 4 + 2) * BM + r] -= v.z;
                    Rs[(dg * 64 + i * 4 + 3) * BM + r] -= v.w;
                }
            }
            // the next loop-head __syncthreads orders this update before stage s+1 compute
        }
    }
    #undef STAGE_B

    // quantised output: out[row] = ((cb0[c0] + cb1[c1]) + cb2[c2]) + cb3[c3]
    // (matches the reference scan's sequential total accumulation order)
    if (writeQ) {
        #pragma unroll
        for (int rr = 0; rr < 8; rr++) {
            int row = w * 8 + rr;
            int c0 = codes_all[row];
            int c1 = codes_all[BM + row];
            int c2 = codes_all[2 * BM + row];
            int c3 = codes_all[3 * BM + row];
            const float4* q0 = (const float4*)(cb + (size_t)c0 * DD);
            const float4* q1 = (const float4*)(cb + ((size_t)KK + c1) * DD);
            const float4* q2 = (const float4*)(cb + ((size_t)2 * KK + c2) * DD);
            const float4* q3 = (const float4*)(cb + ((size_t)3 * KK + c3) * DD);
            float4* orow = (float4*)(outQ + (rowBase + row) * DD);
            #pragma unroll
            for (int dq = 0; dq < 2; dq++) {
                int idx = lane + dq * 32;
                float4 v0 = q0[idx], v1 = q1[idx], v2 = q2[idx], v3 = q3[idx];
                float4 o;
                o.x = ((v0.x + v1.x) + v2.x) + v3.x;
                o.y = ((v0.y + v1.y) + v2.y) + v3.y;
                o.z = ((v0.z + v1.z) + v2.z) + v3.z;
                o.w = ((v0.w + v1.w) + v2.w) + v3.w;
                orow[idx] = o;
            }
        }
    }
}

// ---------------- launch ----------------
extern "C" void kernel_launch(void* const* d_in, const int* in_sizes, int n_in,
                              void* d_out, int out_size) {
    const float* x  = (const float*)d_in[0];
    const float* cb = (const float*)d_in[1];
    float* out = (float*)d_out;

    const long QE = (long)NTOT * DD;
    const long CE = (long)NTOT * NQ;

    int writeQ = (out_size >= QE) ? 1 : 0;
    float* outCodes = nullptr;
    int writeCodes = 0;
    if ((long)out_size >= QE + CE) { outCodes = out + QE; writeCodes = 1; }
    else if (!writeQ && (long)out_size >= CE) { outCodes = out; writeCodes = 1; }

    const int SMEM = (DD * BM + 2 * BK * BNC) * 4 + NQ * BM * 4;   // 99328 B
    cudaFuncSetAttribute(rvq_fused_k, cudaFuncAttributeMaxDynamicSharedMemorySize, SMEM);

    float* cbT_ptr = nullptr;
    cudaGetSymbolAddress((void**)&cbT_ptr, g_cbT);

    dim3 tb(32, 8);
    // codebooks [NQ][K][D] -> [NQ][D][K]
    transpose_k<<<dim3(DD / 32, KK / 32, NQ), tb>>>(cb, cbT_ptr, KK, DD,
                                                    (long)KK * DD, (long)DD * KK);
    c2_k<<<(NQ * KK * 32 + 255) / 256, 256>>>(cb);

    rvq_fused_k<<<NTOT / BM, NTHREADS, SMEM>>>(x, cb, out, writeQ, outCodes, writeCodes);
}